// round 10
// baseline (speedup 1.0000x reference)
#include <cuda_runtime.h>
#include <math.h>

typedef unsigned long long ull;
typedef long long ll;

#define NMAX 10000
#define EMAX 100000

__device__ __align__(16) float g_qt[NMAX * 20];  // per-node pre-rotated query
__device__ float g_z[NMAX];                      // softmax denominators
__device__ float g_ex[EMAX];                     // per-edge exp(dot)
__device__ __align__(16) float g_vv[EMAX * 40];  // per-edge value irreps
__device__ int g_is64;                           // edge_index dtype flag

#define INV_SQRT3  0.5773502691896258f
#define INV_SQRT2  0.7071067811865476f
#define INV_SQRT8  0.35355339059327373f
#define INV_SQRT24 0.2041241452319315f
#define INV_SQRT32 0.17677669529663687f
#define INV_SQRT80 0.11180339887498948f

__device__ __forceinline__ ll eidx(const void* ei, int pos) {
    if (g_is64) return ((const ll*)ei)[pos];
    return (ll)((const int*)ei)[pos];
}

// ---------------- packed f32x2 helpers ----------------
__device__ __forceinline__ ull pack2(float a, float b) {
    ull r; asm("mov.b64 %0, {%1,%2};" : "=l"(r) : "f"(a), "f"(b)); return r;
}
__device__ __forceinline__ void fma2(ull& acc, ull w, ull h) {
    asm("fma.rn.f32x2 %0, %1, %2, %0;" : "+l"(acc) : "l"(w), "l"(h));
}
__device__ __forceinline__ ull add2(ull a, ull b) {
    ull r; asm("add.rn.f32x2 %0, %1, %2;" : "=l"(r) : "l"(a), "l"(b)); return r;
}
__device__ __forceinline__ float2 unpack2(ull v) {
    float2 r; asm("mov.b64 {%0,%1}, %2;" : "=f"(r.x), "=f"(r.y) : "l"(v)); return r;
}
__device__ __forceinline__ float hsum2(ull v) {
    float2 a = unpack2(v); return a.x + a.y;
}

struct ull2r { ull a, b; };

// pair-packed h-inner-product for 2 outputs (j = 2g, 2g+1).
// Wg: group base (16 consecutive float4 chunks, chunk h2 = rows 2h2,2h2+1 for both j).
// hh[h2] = {h_2h2, h_2h2+1}. Returns packed {even-h sum, odd-h sum} per output.
// All addresses warp-uniform -> 1 wavefront per LDS.128.
__device__ __forceinline__ ull2r pwchunk(const float* __restrict__ Wg, const ull* hh) {
    ull a0 = 0, a1 = 0, b0 = 0, b1 = 0;
#pragma unroll
    for (int h2 = 0; h2 < 16; h2 += 2) {
        const ulonglong2 c0 = *reinterpret_cast<const ulonglong2*>(Wg + h2 * 4);
        const ulonglong2 c1 = *reinterpret_cast<const ulonglong2*>(Wg + h2 * 4 + 4);
        fma2(a0, c0.x, hh[h2]);     fma2(a1, c0.y, hh[h2]);
        fma2(b0, c1.x, hh[h2 + 1]); fma2(b1, c1.y, hh[h2 + 1]);
    }
    ull2r r; r.a = add2(a0, b0); r.b = add2(a1, b1); return r;
}

// hidden layer, pair-packed: hh[k] = {silu-col 2k, silu-col 2k+1} * 1/sqrt32
__device__ __forceinline__ void compute_hp(const float* __restrict__ W1,
                                           const float* es, ull* hh) {
    ull acc2[16];
#pragma unroll
    for (int x = 0; x < 16; x++) acc2[x] = 0;
#pragma unroll
    for (int i = 0; i < 16; i++) {
        const ull ep = pack2(es[i], es[i]);
#pragma unroll
        for (int x = 0; x < 16; x += 2) {
            const ulonglong2 w = *reinterpret_cast<const ulonglong2*>(W1 + i * 32 + x * 2);
            fma2(acc2[x], w.x, ep);
            fma2(acc2[x + 1], w.y, ep);
        }
    }
#pragma unroll
    for (int x = 0; x < 16; x++) {
        float2 a = unpack2(acc2[x]);
        float t0 = a.x * 0.25f, t1 = a.y * 0.25f;
        float s0 = t0 / (1.f + __expf(-t0)) * INV_SQRT32;
        float s1 = t1 / (1.f + __expf(-t1)) * INV_SQRT32;
        hh[x] = pack2(s0, s1);
    }
}

__device__ __forceinline__ void load_es(float* es, const float* __restrict__ edge_scalars, int e) {
    const float4* p = (const float4*)(edge_scalars + (size_t)e * 16);
#pragma unroll
    for (int t = 0; t < 4; t++) {
        float4 v = p[t];
        es[t * 4 + 0] = v.x; es[t * 4 + 1] = v.y; es[t * 4 + 2] = v.z; es[t * 4 + 3] = v.w;
    }
}

// ---------------- tiny kernels ----------------
__global__ void k_detect(const int* __restrict__ ei32, int twoE) {
    __shared__ int any;
    if (threadIdx.x == 0) any = 0;
    __syncthreads();
    int nchk = (twoE < 2048 ? twoE : 2048);
    for (int i = threadIdx.x; i < nchk / 2; i += blockDim.x)
        if (ei32[2 * i + 1] != 0) any = 1;
    __syncthreads();
    if (threadIdx.x == 0) g_is64 = (any == 0);
}

__global__ void k_zero(float* __restrict__ out, int N) {
    int i = blockIdx.x * blockDim.x + threadIdx.x;
    if (i < N * 40) out[i] = 0.f;
    if (i < N) g_z[i] = 0.f;
}

__global__ void k_query(const float* __restrict__ node_ft, const float* __restrict__ wqs,
                        const float* __restrict__ wqv, const float* __restrict__ wds,
                        const float* __restrict__ wdv, int N) {
    int n = blockIdx.x * blockDim.x + threadIdx.x;
    if (n >= N) return;
    const float* x = node_ft + (size_t)n * 40;
    float xs[16], xv[24];
#pragma unroll
    for (int i = 0; i < 16; i++) xs[i] = x[i];
#pragma unroll
    for (int i = 0; i < 24; i++) xv[i] = x[16 + i];

    float qs[8];
#pragma unroll
    for (int o = 0; o < 8; o++) qs[o] = 0.f;
#pragma unroll
    for (int i = 0; i < 16; i++) {
        const float c = xs[i];
#pragma unroll
        for (int o = 0; o < 8; o++) qs[o] += c * __ldg(wqs + i * 8 + o);
    }
#pragma unroll
    for (int o = 0; o < 8; o++) qs[o] *= 0.25f;

    float qv[12];
#pragma unroll
    for (int o = 0; o < 12; o++) qv[o] = 0.f;
#pragma unroll
    for (int i = 0; i < 8; i++) {
#pragma unroll
        for (int o = 0; o < 4; o++) {
            const float w = __ldg(wqv + i * 4 + o);
            qv[o * 3 + 0] += xv[i * 3 + 0] * w;
            qv[o * 3 + 1] += xv[i * 3 + 1] * w;
            qv[o * 3 + 2] += xv[i * 3 + 2] * w;
        }
    }
#pragma unroll
    for (int o = 0; o < 12; o++) qv[o] *= INV_SQRT8;

    float qt[20];
#pragma unroll
    for (int o = 0; o < 20; o++) qt[o] = 0.f;
#pragma unroll
    for (int i = 0; i < 8; i++) {
        const float c = qs[i];
#pragma unroll
        for (int o = 0; o < 8; o++) qt[o] += c * __ldg(wds + i * 8 + o);
    }
#pragma unroll
    for (int i = 0; i < 4; i++) {
#pragma unroll
        for (int o = 0; o < 4; o++) {
            const float w = __ldg(wdv + i * 4 + o);
            qt[8 + o * 3 + 0] += qv[i * 3 + 0] * w;
            qt[8 + o * 3 + 1] += qv[i * 3 + 1] * w;
            qt[8 + o * 3 + 2] += qv[i * 3 + 2] * w;
        }
    }
    float* dst = g_qt + (size_t)n * 20;
#pragma unroll
    for (int t = 0; t < 20; t++) dst[t] = qt[t];
}

// ================= K kernel: full K TP + logit; 1 thread per edge =================
// smem floats: W1[512] W2 pair-packed[160 groups * 64]
#define KK_SMEM ((512 + 10240) * 4)

__global__ __launch_bounds__(128, 4) void k_K(
    const float* __restrict__ node_ft, const void* __restrict__ ei,
    const float* __restrict__ edge_sh, const float* __restrict__ edge_scalars,
    const float* __restrict__ w1k, const float* __restrict__ w2k, int E) {
    extern __shared__ float sm[];
    const int tid = threadIdx.x;
    for (int i = tid * 4; i < 512; i += 512) *(float4*)(sm + i) = *(const float4*)(w1k + i);
    {   // pair-pack: chunk(g,h2) = {W[2h2][2g], W[2h2+1][2g], W[2h2][2g+1], W[2h2+1][2g+1]}
        float4* pk = (float4*)(sm + 512);
        for (int idx = tid; idx < 160 * 16; idx += 128) {
            const int g = idx >> 4, h2 = idx & 15;
            const float* r0 = w2k + (2 * h2) * 320 + 2 * g;
            float2 a = *(const float2*)r0;
            float2 b = *(const float2*)(r0 + 320);
            pk[idx] = make_float4(a.x, b.x, a.y, b.y);
        }
    }
    __syncthreads();

    int e = blockIdx.x * 128 + tid;
    const bool valid = (e < E);
    if (!valid) e = E - 1;

    const ll snd = eidx(ei, e);
    const ll rcv = eidx(ei, E + e);

    const float4 shq = *(const float4*)(edge_sh + (size_t)e * 4);
    const float shs = shq.x, sh0 = shq.y, sh1 = shq.z, sh2 = shq.w;

    ull hh[16];
    {
        float es[16];
        load_es(es, edge_scalars, e);
        compute_hp(sm, es, hh);
    }

    const float* W = sm + 512;
    ull accP[8], t3P[4];
#pragma unroll
    for (int o = 0; o < 8; o++) accP[o] = 0;
#pragma unroll
    for (int o = 0; o < 4; o++) t3P[o] = 0;

    // -------- phase A: xs (paths 1, 3) --------
    {
        float xs[16];
        const float4* q = (const float4*)(node_ft + (size_t)snd * 40);
#pragma unroll
        for (int t = 0; t < 4; t++) {
            float4 v = q[t];
            xs[t * 4 + 0] = v.x; xs[t * 4 + 1] = v.y; xs[t * 4 + 2] = v.z; xs[t * 4 + 3] = v.w;
        }
#pragma unroll
        for (int i = 0; i < 16; i++) {    // path1: groups i*4+og, outputs o=2og,2og+1
            const float c = xs[i] * shs;
            const ull cc = pack2(c, c);
#pragma unroll
            for (int og = 0; og < 4; og++) {
                ull2r w = pwchunk(W + (i * 4 + og) * 64, hh);
                fma2(accP[2 * og], w.a, cc);
                fma2(accP[2 * og + 1], w.b, cc);
            }
        }
#pragma unroll
        for (int i = 0; i < 16; i++) {    // path3: groups 96 + i*2 + og, outputs o<4
            const ull cc = pack2(xs[i], xs[i]);
#pragma unroll
            for (int og = 0; og < 2; og++) {
                ull2r w = pwchunk(W + (96 + i * 2 + og) * 64, hh);
                fma2(t3P[2 * og], w.a, cc);
                fma2(t3P[2 * og + 1], w.b, cc);
            }
        }
    }

    // kv packed accumulators (init from path3 x shv)
    ull kvP[12];
    {
        const ull s0 = pack2(sh0, sh0), s1 = pack2(sh1, sh1), s2 = pack2(sh2, sh2);
#pragma unroll
        for (int o = 0; o < 4; o++) {
            kvP[o * 3 + 0] = 0; fma2(kvP[o * 3 + 0], t3P[o], s0);
            kvP[o * 3 + 1] = 0; fma2(kvP[o * 3 + 1], t3P[o], s1);
            kvP[o * 3 + 2] = 0; fma2(kvP[o * 3 + 2], t3P[o], s2);
        }
    }

    // -------- phase B: xv (paths 2, 4, 5) --------
    {
        float xv[24];
        const float4* q = (const float4*)(node_ft + (size_t)snd * 40 + 16);
#pragma unroll
        for (int t = 0; t < 6; t++) {
            float4 v = q[t];
            xv[t * 4 + 0] = v.x; xv[t * 4 + 1] = v.y; xv[t * 4 + 2] = v.z; xv[t * 4 + 3] = v.w;
        }
#pragma unroll
        for (int i = 0; i < 8; i++) {     // path2: groups 64 + i*4 + og
            const float c = (xv[i * 3] * sh0 + xv[i * 3 + 1] * sh1 + xv[i * 3 + 2] * sh2) * INV_SQRT3;
            const ull cc = pack2(c, c);
#pragma unroll
            for (int og = 0; og < 4; og++) {
                ull2r w = pwchunk(W + (64 + i * 4 + og) * 64, hh);
                fma2(accP[2 * og], w.a, cc);
                fma2(accP[2 * og + 1], w.b, cc);
            }
        }
#pragma unroll
        for (int i = 0; i < 8; i++) {     // path4: groups 128 + i*2 + og
            const ull c0 = pack2(xv[i * 3] * shs, xv[i * 3] * shs);
            const ull c1 = pack2(xv[i * 3 + 1] * shs, xv[i * 3 + 1] * shs);
            const ull c2 = pack2(xv[i * 3 + 2] * shs, xv[i * 3 + 2] * shs);
#pragma unroll
            for (int og = 0; og < 2; og++) {
                ull2r w = pwchunk(W + (128 + i * 2 + og) * 64, hh);
                fma2(kvP[(2 * og) * 3 + 0], w.a, c0);
                fma2(kvP[(2 * og) * 3 + 1], w.a, c1);
                fma2(kvP[(2 * og) * 3 + 2], w.a, c2);
                fma2(kvP[(2 * og + 1) * 3 + 0], w.b, c0);
                fma2(kvP[(2 * og + 1) * 3 + 1], w.b, c1);
                fma2(kvP[(2 * og + 1) * 3 + 2], w.b, c2);
            }
        }
#pragma unroll
        for (int i = 0; i < 8; i++) {     // path5: groups 144 + i*2 + og (cross)
            const float v0 = xv[i * 3], v1 = xv[i * 3 + 1], v2 = xv[i * 3 + 2];
            const float p0 = (v1 * sh2 - v2 * sh1) * INV_SQRT2;
            const float p1 = (v2 * sh0 - v0 * sh2) * INV_SQRT2;
            const float p2 = (v0 * sh1 - v1 * sh0) * INV_SQRT2;
            const ull c0 = pack2(p0, p0), c1 = pack2(p1, p1), c2 = pack2(p2, p2);
#pragma unroll
            for (int og = 0; og < 2; og++) {
                ull2r w = pwchunk(W + (144 + i * 2 + og) * 64, hh);
                fma2(kvP[(2 * og) * 3 + 0], w.a, c0);
                fma2(kvP[(2 * og) * 3 + 1], w.a, c1);
                fma2(kvP[(2 * og) * 3 + 2], w.a, c2);
                fma2(kvP[(2 * og + 1) * 3 + 0], w.b, c0);
                fma2(kvP[(2 * og + 1) * 3 + 1], w.b, c1);
                fma2(kvP[(2 * og + 1) * 3 + 2], w.b, c2);
            }
        }
    }

    if (valid) {
        const float* qt = g_qt + (size_t)rcv * 20;
        float dS = 0.f, dV = 0.f;
#pragma unroll
        for (int o = 0; o < 8; o++) dS += qt[o] * hsum2(accP[o]);
#pragma unroll
        for (int o = 0; o < 12; o++) dV += qt[8 + o] * hsum2(kvP[o]);
        const float dot = (dS * INV_SQRT24 + dV * (INV_SQRT32 * INV_SQRT3)) * INV_SQRT80;
        const float exv = __expf(dot);
        g_ex[e] = exv;
        atomicAdd(&g_z[rcv], exv);
    }
}

// ================= Vs kernel: 16 V scalar outputs; 1 thread per edge =================
// V slice j in [0,384): path1 j=i*16+o, path2 j=256+i*16+o. 192 groups.
#define VS_SMEM ((512 + 12288) * 4)

__global__ __launch_bounds__(128, 4) void k_Vs(
    const float* __restrict__ node_ft, const void* __restrict__ ei,
    const float* __restrict__ edge_sh, const float* __restrict__ edge_scalars,
    const float* __restrict__ w1v, const float* __restrict__ w2v, int E) {
    extern __shared__ float sm[];
    const int tid = threadIdx.x;
    for (int i = tid * 4; i < 512; i += 512) *(float4*)(sm + i) = *(const float4*)(w1v + i);
    {
        float4* pk = (float4*)(sm + 512);
        for (int idx = tid; idx < 192 * 16; idx += 128) {
            const int g = idx >> 4, h2 = idx & 15;
            const float* r0 = w2v + (2 * h2) * 640 + 2 * g;
            float2 a = *(const float2*)r0;
            float2 b = *(const float2*)(r0 + 640);
            pk[idx] = make_float4(a.x, b.x, a.y, b.y);
        }
    }
    __syncthreads();

    int e = blockIdx.x * 128 + tid;
    const bool valid = (e < E);
    if (!valid) e = E - 1;
    const ll snd = eidx(ei, e);

    const float4 shq = *(const float4*)(edge_sh + (size_t)e * 4);
    const float shs = shq.x, sh0 = shq.y, sh1 = shq.z, sh2 = shq.w;

    ull hh[16];
    {
        float es[16];
        load_es(es, edge_scalars, e);
        compute_hp(sm, es, hh);
    }

    const float* W = sm + 512;
    ull accP[8]; ull accP2[8];
#pragma unroll
    for (int o = 0; o < 8; o++) { accP[o] = 0; accP2[o] = 0; }

    {   // phase A: xs, path1 (groups i*8+og, outputs 2og,2og+1)
        float xs[16];
        const float4* q = (const float4*)(node_ft + (size_t)snd * 40);
#pragma unroll
        for (int t = 0; t < 4; t++) {
            float4 v = q[t];
            xs[t * 4 + 0] = v.x; xs[t * 4 + 1] = v.y; xs[t * 4 + 2] = v.z; xs[t * 4 + 3] = v.w;
        }
#pragma unroll
        for (int i = 0; i < 16; i++) {
            const float c = xs[i] * shs;
            const ull cc = pack2(c, c);
#pragma unroll
            for (int og = 0; og < 4; og++) {
                ull2r w = pwchunk(W + (i * 8 + og) * 64, hh);
                fma2(accP[2 * og], w.a, cc);
                fma2(accP[2 * og + 1], w.b, cc);
            }
#pragma unroll
            for (int og = 4; og < 8; og++) {
                ull2r w = pwchunk(W + (i * 8 + og) * 64, hh);
                fma2(accP2[2 * (og - 4)], w.a, cc);
                fma2(accP2[2 * (og - 4) + 1], w.b, cc);
            }
        }
    }
    {   // phase B: xv, path2 (groups 128 + i*8 + og)
        float xv[24];
        const float4* q = (const float4*)(node_ft + (size_t)snd * 40 + 16);
#pragma unroll
        for (int t = 0; t < 6; t++) {
            float4 v = q[t];
            xv[t * 4 + 0] = v.x; xv[t * 4 + 1] = v.y; xv[t * 4 + 2] = v.z; xv[t * 4 + 3] = v.w;
        }
#pragma unroll
        for (int i = 0; i < 8; i++) {
            const float c = (xv[i * 3] * sh0 + xv[i * 3 + 1] * sh1 + xv[i * 3 + 2] * sh2) * INV_SQRT3;
            const ull cc = pack2(c, c);
#pragma unroll
            for (int og = 0; og < 4; og++) {
                ull2r w = pwchunk(W + (128 + i * 8 + og) * 64, hh);
                fma2(accP[2 * og], w.a, cc);
                fma2(accP[2 * og + 1], w.b, cc);
            }
#pragma unroll
            for (int og = 4; og < 8; og++) {
                ull2r w = pwchunk(W + (128 + i * 8 + og) * 64, hh);
                fma2(accP2[2 * (og - 4)], w.a, cc);
                fma2(accP2[2 * (og - 4) + 1], w.b, cc);
            }
        }
    }
    if (valid) {
        float* dst = g_vv + (size_t)e * 40;
#pragma unroll
        for (int t = 0; t < 2; t++)
            *(float4*)(dst + t * 4) = make_float4(hsum2(accP[t * 4 + 0]) * INV_SQRT24,
                                                  hsum2(accP[t * 4 + 1]) * INV_SQRT24,
                                                  hsum2(accP[t * 4 + 2]) * INV_SQRT24,
                                                  hsum2(accP[t * 4 + 3]) * INV_SQRT24);
#pragma unroll
        for (int t = 0; t < 2; t++)
            *(float4*)(dst + 8 + t * 4) = make_float4(hsum2(accP2[t * 4 + 0]) * INV_SQRT24,
                                                      hsum2(accP2[t * 4 + 1]) * INV_SQRT24,
                                                      hsum2(accP2[t * 4 + 2]) * INV_SQRT24,
                                                      hsum2(accP2[t * 4 + 3]) * INV_SQRT24);
    }
}

// ================= Vv kernel: 8 V vector outputs (paths 3,4,5); 1 thread per edge =================
// slice j in [384,640) -> local: path3 i*8+o, path4 128+i*8+o, path5 192+i*8+o. 128 groups.
#define VV_SMEM ((512 + 8192) * 4)

__global__ __launch_bounds__(128, 4) void k_Vv(
    const float* __restrict__ node_ft, const void* __restrict__ ei,
    const float* __restrict__ edge_sh, const float* __restrict__ edge_scalars,
    const float* __restrict__ w1v, const float* __restrict__ w2v, int E) {
    extern __shared__ float sm[];
    const int tid = threadIdx.x;
    for (int i = tid * 4; i < 512; i += 512) *(float4*)(sm + i) = *(const float4*)(w1v + i);
    {
        float4* pk = (float4*)(sm + 512);
        for (int idx = tid; idx < 128 * 16; idx += 128) {
            const int g = idx >> 4, h2 = idx & 15;
            const float* r0 = w2v + (2 * h2) * 640 + 384 + 2 * g;
            float2 a = *(const float2*)r0;
            float2 b = *(const float2*)(r0 + 640);
            pk[idx] = make_float4(a.x, b.x, a.y, b.y);
        }
    }
    __syncthreads();

    int e = blockIdx.x * 128 + tid;
    const bool valid = (e < E);
    if (!valid) e = E - 1;
    const ll snd = eidx(ei, e);

    const float4 shq = *(const float4*)(edge_sh + (size_t)e * 4);
    const float shs = shq.x, sh0 = shq.y, sh1 = shq.z, sh2 = shq.w;

    ull hh[16];
    {
        float es[16];
        load_es(es, edge_scalars, e);
        compute_hp(sm, es, hh);
    }

    const float* W = sm + 512;
    ull t3P[8];
#pragma unroll
    for (int o = 0; o < 8; o++) t3P[o] = 0;

    {   // phase A: xs, path3 (groups i*4+og, outputs 2og,2og+1)
        float xs[16];
        const float4* q = (const float4*)(node_ft + (size_t)snd * 40);
#pragma unroll
        for (int t = 0; t < 4; t++) {
            float4 v = q[t];
            xs[t * 4 + 0] = v.x; xs[t * 4 + 1] = v.y; xs[t * 4 + 2] = v.z; xs[t * 4 + 3] = v.w;
        }
#pragma unroll
        for (int i = 0; i < 16; i++) {
            const ull cc = pack2(xs[i], xs[i]);
#pragma unroll
            for (int og = 0; og < 4; og++) {
                ull2r w = pwchunk(W + (i * 4 + og) * 64, hh);
                fma2(t3P[2 * og], w.a, cc);
                fma2(t3P[2 * og + 1], w.b, cc);
            }
        }
    }

    ull vvP[24];
    {
        const ull s0 = pack2(sh0, sh0), s1 = pack2(sh1, sh1), s2 = pack2(sh2, sh2);
#pragma unroll
        for (int o = 0; o < 8; o++) {
            vvP[o * 3 + 0] = 0; fma2(vvP[o * 3 + 0], t3P[o], s0);
            vvP[o * 3 + 1] = 0; fma2(vvP[o * 3 + 1], t3P[o], s1);
            vvP[o * 3 + 2] = 0; fma2(vvP[o * 3 + 2], t3P[o], s2);
        }
    }

    {   // phase B: xv, paths 4, 5
        float xv[24];
        const float4* q = (const float4*)(node_ft + (size_t)snd * 40 + 16);
#pragma unroll
        for (int t = 0; t < 6; t++) {
            float4 v = q[t];
            xv[t * 4 + 0] = v.x; xv[t * 4 + 1] = v.y; xv[t * 4 + 2] = v.z; xv[t * 4 + 3] = v.w;
        }
#pragma unroll
        for (int i = 0; i < 8; i++) {     // path4: groups 64 + i*4 + og
            const ull c0 = pack2(xv[i * 3] * shs, xv[i * 3] * shs);
            const ull c1 = pack2(xv[i * 3 + 1] * shs, xv[i * 3 + 1] * shs);
            const ull c2 = pack2(xv[i * 3 + 2] * shs, xv[i * 3 + 2] * shs);
#pragma unroll
            for (int og = 0; og < 4; og++) {
                ull2r w = pwchunk(W + (64 + i * 4 + og) * 64, hh);
                fma2(vvP[(2 * og) * 3 + 0], w.a, c0);
                fma2(vvP[(2 * og) * 3 + 1], w.a, c1);
                fma2(vvP[(2 * og) * 3 + 2], w.a, c2);
                fma2(vvP[(2 * og + 1) * 3 + 0], w.b, c0);
                fma2(vvP[(2 * og + 1) * 3 + 1], w.b, c1);
                fma2(vvP[(2 * og + 1) * 3 + 2], w.b, c2);
            }
        }
#pragma unroll
        for (int i = 0; i < 8; i++) {     // path5: groups 96 + i*4 + og
            const float v0 = xv[i * 3], v1 = xv[i * 3 + 1], v2 = xv[i * 3 + 2];
            const float p0 = (v1 * sh2 - v2 * sh1) * INV_SQRT2;
            const float p1 = (v2 * sh0 - v0 * sh2) * INV_SQRT2;
            const float p2 = (v0 * sh1 - v1 * sh0) * INV_SQRT2;
            const ull c0 = pack2(p0, p0), c1 = pack2(p1, p1), c2 = pack2(p2, p2);
#pragma unroll
            for (int og = 0; og < 4; og++) {
                ull2r w = pwchunk(W + (96 + i * 4 + og) * 64, hh);
                fma2(vvP[(2 * og) * 3 + 0], w.a, c0);
                fma2(vvP[(2 * og) * 3 + 1], w.a, c1);
                fma2(vvP[(2 * og) * 3 + 2], w.a, c2);
                fma2(vvP[(2 * og + 1) * 3 + 0], w.b, c0);
                fma2(vvP[(2 * og + 1) * 3 + 1], w.b, c1);
                fma2(vvP[(2 * og + 1) * 3 + 2], w.b, c2);
            }
        }
    }

    if (valid) {
        float* dst = g_vv + (size_t)e * 40 + 16;
#pragma unroll
        for (int t = 0; t < 6; t++)
            *(float4*)(dst + t * 4) = make_float4(hsum2(vvP[t * 4 + 0]) * INV_SQRT32,
                                                  hsum2(vvP[t * 4 + 1]) * INV_SQRT32,
                                                  hsum2(vvP[t * 4 + 2]) * INV_SQRT32,
                                                  hsum2(vvP[t * 4 + 3]) * INV_SQRT32);
    }
}

// ---------------- scatter: softmax normalize + vector reduction ----------------
__global__ void k_scatter(const void* __restrict__ ei, float* __restrict__ out, int E) {
    int e = blockIdx.x * blockDim.x + threadIdx.x;
    if (e >= E) return;
    const ll r = eidx(ei, E + e);
    const float a = sqrtf(g_ex[e] / g_z[r]);
    const float4* v = (const float4*)(g_vv + (size_t)e * 40);
    float* o = out + (size_t)r * 40;
#pragma unroll
    for (int t = 0; t < 10; t++) {
        float4 w = v[t];
        asm volatile("red.global.add.v4.f32 [%0], {%1, %2, %3, %4};"
                     :: "l"(o + t * 4), "f"(a * w.x), "f"(a * w.y), "f"(a * w.z), "f"(a * w.w)
                     : "memory");
    }
}

extern "C" void kernel_launch(void* const* d_in, const int* in_sizes, int n_in,
                              void* d_out, int out_size) {
    const float* node_ft      = (const float*)d_in[0];
    const void*  ei           = d_in[1];
    const float* edge_sh      = (const float*)d_in[2];
    const float* edge_scalars = (const float*)d_in[3];
    const float* wqs          = (const float*)d_in[4];
    const float* wqv          = (const float*)d_in[5];
    const float* fckw1        = (const float*)d_in[6];
    const float* fckw2        = (const float*)d_in[7];
    const float* fcvw1        = (const float*)d_in[8];
    const float* fcvw2        = (const float*)d_in[9];
    const float* wds          = (const float*)d_in[10];
    const float* wdv          = (const float*)d_in[11];
    float* out = (float*)d_out;

    const int N = in_sizes[0] / 40;
    const int E = in_sizes[1] / 2;
    const int gE = (E + 127) / 128;

    cudaFuncSetAttribute(k_K,  cudaFuncAttributeMaxDynamicSharedMemorySize, KK_SMEM);
    cudaFuncSetAttribute(k_Vs, cudaFuncAttributeMaxDynamicSharedMemorySize, VS_SMEM);
    cudaFuncSetAttribute(k_Vv, cudaFuncAttributeMaxDynamicSharedMemorySize, VV_SMEM);

    k_detect<<<1, 256>>>((const int*)ei, 2 * E);
    k_zero<<<(N * 40 + 255) / 256, 256>>>(out, N);
    k_query<<<(N + 255) / 256, 256>>>(node_ft, wqs, wqv, wds, wdv, N);
    k_K<<<gE, 128, KK_SMEM>>>(node_ft, ei, edge_sh, edge_scalars, fckw1, fckw2, E);
    k_Vs<<<gE, 128, VS_SMEM>>>(node_ft, ei, edge_sh, edge_scalars, fcvw1, fcvw2, E);
    k_Vv<<<gE, 128, VV_SMEM>>>(node_ft, ei, edge_sh, edge_scalars, fcvw1, fcvw2, E);
    k_scatter<<<(E + 255) / 256, 256>>>(ei, out, E);
}

// round 11
// speedup vs baseline: 1.3030x; 1.3030x over previous
#include <cuda_runtime.h>
#include <math.h>

typedef unsigned long long ull;
typedef long long ll;

#define NMAX 10000
#define EMAX 100000

__device__ __align__(16) float g_qt[NMAX * 20];  // per-node pre-rotated query
__device__ float g_z[NMAX];                      // softmax denominators
__device__ float g_ex[EMAX];                     // per-edge exp(dot)
__device__ __align__(16) float g_vv[EMAX * 40];  // per-edge value irreps
__device__ int g_is64;                           // edge_index dtype flag

#define INV_SQRT3  0.5773502691896258f
#define INV_SQRT2  0.7071067811865476f
#define INV_SQRT8  0.35355339059327373f
#define INV_SQRT24 0.2041241452319315f
#define INV_SQRT32 0.17677669529663687f
#define INV_SQRT80 0.11180339887498948f

__device__ __forceinline__ ll eidx(const void* ei, int pos) {
    if (g_is64) return ((const ll*)ei)[pos];
    return (ll)((const int*)ei)[pos];
}

// ---------------- packed f32x2 helpers ----------------
__device__ __forceinline__ ull pack2(float a, float b) {
    ull r; asm("mov.b64 %0, {%1,%2};" : "=l"(r) : "f"(a), "f"(b)); return r;
}
__device__ __forceinline__ void fma2(ull& acc, ull w, ull h) {
    asm("fma.rn.f32x2 %0, %1, %2, %0;" : "+l"(acc) : "l"(w), "l"(h));
}
__device__ __forceinline__ float2 unpack2(ull v) {
    float2 r; asm("mov.b64 {%0,%1}, %2;" : "=f"(r.x), "=f"(r.y) : "l"(v)); return r;
}
__device__ __forceinline__ float hsum2(ull v) {
    float2 a = unpack2(v); return a.x + a.y;
}
__device__ __forceinline__ float comb(float v) {
    return v + __shfl_xor_sync(0xffffffffu, v, 1);
}

// group chunk: packed (over this lane's h-half) partial weights for outputs j=2g, 2g+1,
// consumed simultaneously for two edges' hidden vectors h0, h1.
// Wb = W + g*64 + par*4. Chunk k: {W[h0][2g], W[h0+1][2g], W[h0][2g+1], W[h0+1][2g+1]},
// h0 = par*16 + 2k. Even/odd lanes read adjacent 16B (same 32B sector).
__device__ __forceinline__ void gch(const float* __restrict__ Wb,
                                    const ull* h0, const ull* h1,
                                    ull& w0e0, ull& w1e0, ull& w0e1, ull& w1e1) {
    ull a0 = 0, b0 = 0, a1 = 0, b1 = 0;
#pragma unroll
    for (int k = 0; k < 8; k++) {
        const ulonglong2 c = *reinterpret_cast<const ulonglong2*>(Wb + k * 8);
        fma2(a0, c.x, h0[k]); fma2(b0, c.y, h0[k]);
        fma2(a1, c.x, h1[k]); fma2(b1, c.y, h1[k]);
    }
    w0e0 = a0; w1e0 = b0; w0e1 = a1; w1e1 = b1;
}

// hidden half for one edge: this lane computes local cols [par*16, par*16+16),
// output hh[k] = {col 2k, col 2k+1} (adjacent pack), scaled by 1/sqrt32.
__device__ __forceinline__ void compute_h16p(const float* __restrict__ W1,
                                             const float* es, ull* hh, int par) {
    ull acc2[8];
#pragma unroll
    for (int x = 0; x < 8; x++) acc2[x] = 0;
    const float* base = W1 + par * 16;
#pragma unroll
    for (int i = 0; i < 16; i++) {
        const ull ep = pack2(es[i], es[i]);
#pragma unroll
        for (int xl = 0; xl < 8; xl += 2) {
            const ulonglong2 w = *reinterpret_cast<const ulonglong2*>(base + i * 32 + xl * 2);
            fma2(acc2[xl], w.x, ep);
            fma2(acc2[xl + 1], w.y, ep);
        }
    }
#pragma unroll
    for (int x = 0; x < 8; x++) {
        float2 a = unpack2(acc2[x]);
        float t0 = a.x * 0.25f, t1 = a.y * 0.25f;
        float s0 = t0 / (1.f + __expf(-t0)) * INV_SQRT32;
        float s1 = t1 / (1.f + __expf(-t1)) * INV_SQRT32;
        hh[x] = pack2(s0, s1);
    }
}

__device__ __forceinline__ void load_es(float* es, const float* __restrict__ edge_scalars, int e) {
    const float4* p = (const float4*)(edge_scalars + (size_t)e * 16);
#pragma unroll
    for (int t = 0; t < 4; t++) {
        float4 v = p[t];
        es[t * 4 + 0] = v.x; es[t * 4 + 1] = v.y; es[t * 4 + 2] = v.z; es[t * 4 + 3] = v.w;
    }
}

// pair-pack a W2 slice into smem: dst float4 idx = (g*8+k)*2+par,
// value = {W[h0][C0+2g], W[h0+1][C0+2g], W[h0][C0+2g+1], W[h0+1][C0+2g+1]}, h0 = par*16+2k.
template <int NG, int S, int C0>
__device__ __forceinline__ void pack_w2(float4* pk, const float* __restrict__ w2, int tid) {
    for (int idx = tid; idx < NG * 16; idx += 128) {
        const int p = idx & 1, t = idx >> 1, k = t & 7, g = t >> 3;
        const float* r0 = w2 + (p * 16 + 2 * k) * S + C0 + 2 * g;
        float2 a = *(const float2*)r0;
        float2 b = *(const float2*)(r0 + S);
        pk[idx] = make_float4(a.x, b.x, a.y, b.y);
    }
}

// ---------------- tiny kernels ----------------
__global__ void k_detect(const int* __restrict__ ei32, int twoE) {
    __shared__ int any;
    if (threadIdx.x == 0) any = 0;
    __syncthreads();
    int nchk = (twoE < 2048 ? twoE : 2048);
    for (int i = threadIdx.x; i < nchk / 2; i += blockDim.x)
        if (ei32[2 * i + 1] != 0) any = 1;
    __syncthreads();
    if (threadIdx.x == 0) g_is64 = (any == 0);
}

__global__ void k_zero(float* __restrict__ out, int N) {
    int i = blockIdx.x * blockDim.x + threadIdx.x;
    if (i < N * 40) out[i] = 0.f;
    if (i < N) g_z[i] = 0.f;
}

__global__ void k_query(const float* __restrict__ node_ft, const float* __restrict__ wqs,
                        const float* __restrict__ wqv, const float* __restrict__ wds,
                        const float* __restrict__ wdv, int N) {
    int n = blockIdx.x * blockDim.x + threadIdx.x;
    if (n >= N) return;
    const float* x = node_ft + (size_t)n * 40;
    float xs[16], xv[24];
#pragma unroll
    for (int i = 0; i < 16; i++) xs[i] = x[i];
#pragma unroll
    for (int i = 0; i < 24; i++) xv[i] = x[16 + i];

    float qs[8];
#pragma unroll
    for (int o = 0; o < 8; o++) qs[o] = 0.f;
#pragma unroll
    for (int i = 0; i < 16; i++) {
        const float c = xs[i];
#pragma unroll
        for (int o = 0; o < 8; o++) qs[o] += c * __ldg(wqs + i * 8 + o);
    }
#pragma unroll
    for (int o = 0; o < 8; o++) qs[o] *= 0.25f;

    float qv[12];
#pragma unroll
    for (int o = 0; o < 12; o++) qv[o] = 0.f;
#pragma unroll
    for (int i = 0; i < 8; i++) {
#pragma unroll
        for (int o = 0; o < 4; o++) {
            const float w = __ldg(wqv + i * 4 + o);
            qv[o * 3 + 0] += xv[i * 3 + 0] * w;
            qv[o * 3 + 1] += xv[i * 3 + 1] * w;
            qv[o * 3 + 2] += xv[i * 3 + 2] * w;
        }
    }
#pragma unroll
    for (int o = 0; o < 12; o++) qv[o] *= INV_SQRT8;

    float qt[20];
#pragma unroll
    for (int o = 0; o < 20; o++) qt[o] = 0.f;
#pragma unroll
    for (int i = 0; i < 8; i++) {
        const float c = qs[i];
#pragma unroll
        for (int o = 0; o < 8; o++) qt[o] += c * __ldg(wds + i * 8 + o);
    }
#pragma unroll
    for (int i = 0; i < 4; i++) {
#pragma unroll
        for (int o = 0; o < 4; o++) {
            const float w = __ldg(wdv + i * 4 + o);
            qt[8 + o * 3 + 0] += qv[i * 3 + 0] * w;
            qt[8 + o * 3 + 1] += qv[i * 3 + 1] * w;
            qt[8 + o * 3 + 2] += qv[i * 3 + 2] * w;
        }
    }
    float* dst = g_qt + (size_t)n * 20;
#pragma unroll
    for (int t = 0; t < 20; t++) dst[t] = qt[t];
}

// ================= K kernel: full K TP + logit; lane pair = 2 edges, h-split =================
// smem floats: W1[512] W2 packed[160 groups * 64]
#define KK_SMEM ((512 + 10240) * 4)

__global__ __launch_bounds__(128, 4) void k_K(
    const float* __restrict__ node_ft, const void* __restrict__ ei,
    const float* __restrict__ edge_sh, const float* __restrict__ edge_scalars,
    const float* __restrict__ w1k, const float* __restrict__ w2k, int E) {
    extern __shared__ float sm[];
    const int tid = threadIdx.x;
    for (int i = tid * 4; i < 512; i += 512) *(float4*)(sm + i) = *(const float4*)(w1k + i);
    pack_w2<160, 320, 0>((float4*)(sm + 512), w2k, tid);
    __syncthreads();

    const int par = tid & 1;
    const int e0 = blockIdx.x * 128 + (tid >> 1) * 2;
    const int e1 = e0 + 1;
    const bool v0 = (e0 < E), v1 = (e1 < E);
    const int ec0 = v0 ? e0 : 0, ec1 = v1 ? e1 : 0;

    const ll snd0 = eidx(ei, ec0), snd1 = eidx(ei, ec1);
    const float4 sq0 = *(const float4*)(edge_sh + (size_t)ec0 * 4);
    const float4 sq1 = *(const float4*)(edge_sh + (size_t)ec1 * 4);

    ull hh0[8], hh1[8];
    {
        float es[16];
        load_es(es, edge_scalars, ec0); compute_h16p(sm, es, hh0, par);
        load_es(es, edge_scalars, ec1); compute_h16p(sm, es, hh1, par);
    }

    const float* W = sm + 512 + par * 4;
    const float* nf0 = node_ft + (size_t)snd0 * 40;
    const float* nf1 = node_ft + (size_t)snd1 * 40;

    ull aS0[8], aS1[8], t3P0[4], t3P1[4];
#pragma unroll
    for (int o = 0; o < 8; o++) { aS0[o] = 0; aS1[o] = 0; }
#pragma unroll
    for (int o = 0; o < 4; o++) { t3P0[o] = 0; t3P1[o] = 0; }

    // -------- phase A: xs (paths 1, 3) --------
#pragma unroll
    for (int i = 0; i < 16; i++) {
        const float x0 = __ldg(nf0 + i), x1 = __ldg(nf1 + i);
        const float c0 = x0 * sq0.x, c1 = x1 * sq1.x;
        const ull cc0 = pack2(c0, c0), cc1 = pack2(c1, c1);
#pragma unroll
        for (int og = 0; og < 4; og++) {       // path1: g = i*4+og
            ull w00, w10, w01, w11;
            gch(W + (i * 4 + og) * 64, hh0, hh1, w00, w10, w01, w11);
            fma2(aS0[2 * og], w00, cc0); fma2(aS0[2 * og + 1], w10, cc0);
            fma2(aS1[2 * og], w01, cc1); fma2(aS1[2 * og + 1], w11, cc1);
        }
        const ull xx0 = pack2(x0, x0), xx1 = pack2(x1, x1);
#pragma unroll
        for (int og = 0; og < 2; og++) {       // path3: g = 96 + i*2 + og
            ull w00, w10, w01, w11;
            gch(W + (96 + i * 2 + og) * 64, hh0, hh1, w00, w10, w01, w11);
            fma2(t3P0[2 * og], w00, xx0); fma2(t3P0[2 * og + 1], w10, xx0);
            fma2(t3P1[2 * og], w01, xx1); fma2(t3P1[2 * og + 1], w11, xx1);
        }
    }

    float kv0[12], kv1[12];
#pragma unroll
    for (int o = 0; o < 4; o++) {
        const float t0 = hsum2(t3P0[o]), t1 = hsum2(t3P1[o]);
        kv0[o * 3 + 0] = t0 * sq0.y; kv0[o * 3 + 1] = t0 * sq0.z; kv0[o * 3 + 2] = t0 * sq0.w;
        kv1[o * 3 + 0] = t1 * sq1.y; kv1[o * 3 + 1] = t1 * sq1.z; kv1[o * 3 + 2] = t1 * sq1.w;
    }

    // -------- phase B: xv (paths 2, 4, 5) --------
#pragma unroll
    for (int i = 0; i < 8; i++) {
        const float a0 = __ldg(nf0 + 16 + i * 3), a1 = __ldg(nf0 + 17 + i * 3), a2 = __ldg(nf0 + 18 + i * 3);
        const float b0 = __ldg(nf1 + 16 + i * 3), b1 = __ldg(nf1 + 17 + i * 3), b2 = __ldg(nf1 + 18 + i * 3);
        {   // path2: g = 64 + i*4 + og
            const float c20 = (a0 * sq0.y + a1 * sq0.z + a2 * sq0.w) * INV_SQRT3;
            const float c21 = (b0 * sq1.y + b1 * sq1.z + b2 * sq1.w) * INV_SQRT3;
            const ull cc0 = pack2(c20, c20), cc1 = pack2(c21, c21);
#pragma unroll
            for (int og = 0; og < 4; og++) {
                ull w00, w10, w01, w11;
                gch(W + (64 + i * 4 + og) * 64, hh0, hh1, w00, w10, w01, w11);
                fma2(aS0[2 * og], w00, cc0); fma2(aS0[2 * og + 1], w10, cc0);
                fma2(aS1[2 * og], w01, cc1); fma2(aS1[2 * og + 1], w11, cc1);
            }
        }
        {   // path4: g = 128 + i*2 + og, coeffs xv*shs per edge
            const float px0 = a0 * sq0.x, py0 = a1 * sq0.x, pz0 = a2 * sq0.x;
            const float px1 = b0 * sq1.x, py1 = b1 * sq1.x, pz1 = b2 * sq1.x;
#pragma unroll
            for (int og = 0; og < 2; og++) {
                ull w00, w10, w01, w11;
                gch(W + (128 + i * 2 + og) * 64, hh0, hh1, w00, w10, w01, w11);
                const float f00 = hsum2(w00), f10 = hsum2(w10);
                const float f01 = hsum2(w01), f11 = hsum2(w11);
                kv0[(2 * og) * 3 + 0] += px0 * f00; kv0[(2 * og) * 3 + 1] += py0 * f00; kv0[(2 * og) * 3 + 2] += pz0 * f00;
                kv0[(2 * og + 1) * 3 + 0] += px0 * f10; kv0[(2 * og + 1) * 3 + 1] += py0 * f10; kv0[(2 * og + 1) * 3 + 2] += pz0 * f10;
                kv1[(2 * og) * 3 + 0] += px1 * f01; kv1[(2 * og) * 3 + 1] += py1 * f01; kv1[(2 * og) * 3 + 2] += pz1 * f01;
                kv1[(2 * og + 1) * 3 + 0] += px1 * f11; kv1[(2 * og + 1) * 3 + 1] += py1 * f11; kv1[(2 * og + 1) * 3 + 2] += pz1 * f11;
            }
        }
        {   // path5: g = 144 + i*2 + og, cross coeffs per edge
            const float px0 = (a1 * sq0.w - a2 * sq0.z) * INV_SQRT2;
            const float py0 = (a2 * sq0.y - a0 * sq0.w) * INV_SQRT2;
            const float pz0 = (a0 * sq0.z - a1 * sq0.y) * INV_SQRT2;
            const float px1 = (b1 * sq1.w - b2 * sq1.z) * INV_SQRT2;
            const float py1 = (b2 * sq1.y - b0 * sq1.w) * INV_SQRT2;
            const float pz1 = (b0 * sq1.z - b1 * sq1.y) * INV_SQRT2;
#pragma unroll
            for (int og = 0; og < 2; og++) {
                ull w00, w10, w01, w11;
                gch(W + (144 + i * 2 + og) * 64, hh0, hh1, w00, w10, w01, w11);
                const float f00 = hsum2(w00), f10 = hsum2(w10);
                const float f01 = hsum2(w01), f11 = hsum2(w11);
                kv0[(2 * og) * 3 + 0] += px0 * f00; kv0[(2 * og) * 3 + 1] += py0 * f00; kv0[(2 * og) * 3 + 2] += pz0 * f00;
                kv0[(2 * og + 1) * 3 + 0] += px0 * f10; kv0[(2 * og + 1) * 3 + 1] += py0 * f10; kv0[(2 * og + 1) * 3 + 2] += pz0 * f10;
                kv1[(2 * og) * 3 + 0] += px1 * f01; kv1[(2 * og) * 3 + 1] += py1 * f01; kv1[(2 * og) * 3 + 2] += pz1 * f01;
                kv1[(2 * og + 1) * 3 + 0] += px1 * f11; kv1[(2 * og + 1) * 3 + 1] += py1 * f11; kv1[(2 * og + 1) * 3 + 2] += pz1 * f11;
            }
        }
    }

    // -------- combine lane pair (sum h-halves), then each lane does its edge --------
    float sS[8], sV[12];
#pragma unroll
    for (int o = 0; o < 8; o++) {
        const float u0 = comb(hsum2(aS0[o]));
        const float u1 = comb(hsum2(aS1[o]));
        sS[o] = par ? u1 : u0;
    }
#pragma unroll
    for (int o = 0; o < 12; o++) {
        const float u0 = comb(kv0[o]);
        const float u1 = comb(kv1[o]);
        sV[o] = par ? u1 : u0;
    }

    const int eMy = par ? ec1 : ec0;
    const bool vMy = par ? v1 : v0;
    if (vMy) {
        const ll rcv = eidx(ei, E + eMy);
        const float* qt = g_qt + (size_t)rcv * 20;
        float dS = 0.f, dV = 0.f;
#pragma unroll
        for (int o = 0; o < 8; o++) dS += __ldg(qt + o) * sS[o];
#pragma unroll
        for (int o = 0; o < 12; o++) dV += __ldg(qt + 8 + o) * sV[o];
        const float dot = (dS * INV_SQRT24 + dV * (INV_SQRT32 * INV_SQRT3)) * INV_SQRT80;
        const float exv = __expf(dot);
        g_ex[eMy] = exv;
        atomicAdd(&g_z[rcv], exv);
    }
}

// ================= Vs kernel: 16 V scalar outputs; lane pair = 2 edges =================
// slice j in [0,384): path1 g = i*8+og, path2 g = 128+i*8+og. 192 groups.
#define VS_SMEM ((512 + 12288) * 4)

__global__ __launch_bounds__(128, 4) void k_Vs(
    const float* __restrict__ node_ft, const void* __restrict__ ei,
    const float* __restrict__ edge_sh, const float* __restrict__ edge_scalars,
    const float* __restrict__ w1v, const float* __restrict__ w2v, int E) {
    extern __shared__ float sm[];
    const int tid = threadIdx.x;
    for (int i = tid * 4; i < 512; i += 512) *(float4*)(sm + i) = *(const float4*)(w1v + i);
    pack_w2<192, 640, 0>((float4*)(sm + 512), w2v, tid);
    __syncthreads();

    const int par = tid & 1;
    const int e0 = blockIdx.x * 128 + (tid >> 1) * 2;
    const int e1 = e0 + 1;
    const bool v0 = (e0 < E), v1 = (e1 < E);
    const int ec0 = v0 ? e0 : 0, ec1 = v1 ? e1 : 0;

    const ll snd0 = eidx(ei, ec0), snd1 = eidx(ei, ec1);
    const float4 sq0 = *(const float4*)(edge_sh + (size_t)ec0 * 4);
    const float4 sq1 = *(const float4*)(edge_sh + (size_t)ec1 * 4);

    ull hh0[8], hh1[8];
    {
        float es[16];
        load_es(es, edge_scalars, ec0); compute_h16p(sm, es, hh0, par);
        load_es(es, edge_scalars, ec1); compute_h16p(sm, es, hh1, par);
    }

    const float* W = sm + 512 + par * 4;
    const float* nf0 = node_ft + (size_t)snd0 * 40;
    const float* nf1 = node_ft + (size_t)snd1 * 40;

    ull aS0[16], aS1[16];
#pragma unroll
    for (int o = 0; o < 16; o++) { aS0[o] = 0; aS1[o] = 0; }

    // phase A: xs, path1 (g = i*8 + og)
#pragma unroll
    for (int i = 0; i < 16; i++) {
        const float x0 = __ldg(nf0 + i), x1 = __ldg(nf1 + i);
        const float c0 = x0 * sq0.x, c1 = x1 * sq1.x;
        const ull cc0 = pack2(c0, c0), cc1 = pack2(c1, c1);
#pragma unroll
        for (int og = 0; og < 8; og++) {
            ull w00, w10, w01, w11;
            gch(W + (i * 8 + og) * 64, hh0, hh1, w00, w10, w01, w11);
            fma2(aS0[2 * og], w00, cc0); fma2(aS0[2 * og + 1], w10, cc0);
            fma2(aS1[2 * og], w01, cc1); fma2(aS1[2 * og + 1], w11, cc1);
        }
    }
    // phase B: xv, path2 (g = 128 + i*8 + og)
#pragma unroll
    for (int i = 0; i < 8; i++) {
        const float a0 = __ldg(nf0 + 16 + i * 3), a1 = __ldg(nf0 + 17 + i * 3), a2 = __ldg(nf0 + 18 + i * 3);
        const float b0 = __ldg(nf1 + 16 + i * 3), b1 = __ldg(nf1 + 17 + i * 3), b2 = __ldg(nf1 + 18 + i * 3);
        const float c20 = (a0 * sq0.y + a1 * sq0.z + a2 * sq0.w) * INV_SQRT3;
        const float c21 = (b0 * sq1.y + b1 * sq1.z + b2 * sq1.w) * INV_SQRT3;
        const ull cc0 = pack2(c20, c20), cc1 = pack2(c21, c21);
#pragma unroll
        for (int og = 0; og < 8; og++) {
            ull w00, w10, w01, w11;
            gch(W + (128 + i * 8 + og) * 64, hh0, hh1, w00, w10, w01, w11);
            fma2(aS0[2 * og], w00, cc0); fma2(aS0[2 * og + 1], w10, cc0);
            fma2(aS1[2 * og], w01, cc1); fma2(aS1[2 * og + 1], w11, cc1);
        }
    }

    float s[16];
#pragma unroll
    for (int o = 0; o < 16; o++) {
        const float u0 = comb(hsum2(aS0[o]));
        const float u1 = comb(hsum2(aS1[o]));
        s[o] = par ? u1 : u0;
    }
    const int eMy = par ? ec1 : ec0;
    const bool vMy = par ? v1 : v0;
    if (vMy) {
        float* dst = g_vv + (size_t)eMy * 40;
#pragma unroll
        for (int t = 0; t < 4; t++)
            *(float4*)(dst + t * 4) = make_float4(s[t * 4 + 0] * INV_SQRT24, s[t * 4 + 1] * INV_SQRT24,
                                                  s[t * 4 + 2] * INV_SQRT24, s[t * 4 + 3] * INV_SQRT24);
    }
}

// ================= Vv kernel: 8 V vector outputs; lane pair = 2 edges =================
// slice local [0,256) = global [384,640): path3 g = i*4+og, path4 g = 64+i*4+og, path5 g = 96+i*4+og
#define VV_SMEM ((512 + 8192) * 4)

__global__ __launch_bounds__(128, 4) void k_Vv(
    const float* __restrict__ node_ft, const void* __restrict__ ei,
    const float* __restrict__ edge_sh, const float* __restrict__ edge_scalars,
    const float* __restrict__ w1v, const float* __restrict__ w2v, int E) {
    extern __shared__ float sm[];
    const int tid = threadIdx.x;
    for (int i = tid * 4; i < 512; i += 512) *(float4*)(sm + i) = *(const float4*)(w1v + i);
    pack_w2<128, 640, 384>((float4*)(sm + 512), w2v, tid);
    __syncthreads();

    const int par = tid & 1;
    const int e0 = blockIdx.x * 128 + (tid >> 1) * 2;
    const int e1 = e0 + 1;
    const bool v0 = (e0 < E), v1 = (e1 < E);
    const int ec0 = v0 ? e0 : 0, ec1 = v1 ? e1 : 0;

    const ll snd0 = eidx(ei, ec0), snd1 = eidx(ei, ec1);
    const float4 sq0 = *(const float4*)(edge_sh + (size_t)ec0 * 4);
    const float4 sq1 = *(const float4*)(edge_sh + (size_t)ec1 * 4);

    ull hh0[8], hh1[8];
    {
        float es[16];
        load_es(es, edge_scalars, ec0); compute_h16p(sm, es, hh0, par);
        load_es(es, edge_scalars, ec1); compute_h16p(sm, es, hh1, par);
    }

    const float* W = sm + 512 + par * 4;
    const float* nf0 = node_ft + (size_t)snd0 * 40;
    const float* nf1 = node_ft + (size_t)snd1 * 40;

    ull t3P0[8], t3P1[8];
#pragma unroll
    for (int o = 0; o < 8; o++) { t3P0[o] = 0; t3P1[o] = 0; }

    // phase A: xs, path3 (g = i*4 + og)
#pragma unroll
    for (int i = 0; i < 16; i++) {
        const float x0 = __ldg(nf0 + i), x1 = __ldg(nf1 + i);
        const ull xx0 = pack2(x0, x0), xx1 = pack2(x1, x1);
#pragma unroll
        for (int og = 0; og < 4; og++) {
            ull w00, w10, w01, w11;
            gch(W + (i * 4 + og) * 64, hh0, hh1, w00, w10, w01, w11);
            fma2(t3P0[2 * og], w00, xx0); fma2(t3P0[2 * og + 1], w10, xx0);
            fma2(t3P1[2 * og], w01, xx1); fma2(t3P1[2 * og + 1], w11, xx1);
        }
    }

    float vv0[24], vv1[24];
#pragma unroll
    for (int o = 0; o < 8; o++) {
        const float t0 = hsum2(t3P0[o]), t1 = hsum2(t3P1[o]);
        vv0[o * 3 + 0] = t0 * sq0.y; vv0[o * 3 + 1] = t0 * sq0.z; vv0[o * 3 + 2] = t0 * sq0.w;
        vv1[o * 3 + 0] = t1 * sq1.y; vv1[o * 3 + 1] = t1 * sq1.z; vv1[o * 3 + 2] = t1 * sq1.w;
    }

    // phase B: xv, paths 4 & 5
#pragma unroll
    for (int i = 0; i < 8; i++) {
        const float a0 = __ldg(nf0 + 16 + i * 3), a1 = __ldg(nf0 + 17 + i * 3), a2 = __ldg(nf0 + 18 + i * 3);
        const float b0 = __ldg(nf1 + 16 + i * 3), b1 = __ldg(nf1 + 17 + i * 3), b2 = __ldg(nf1 + 18 + i * 3);
        {   // path4: g = 64 + i*4 + og
            const float px0 = a0 * sq0.x, py0 = a1 * sq0.x, pz0 = a2 * sq0.x;
            const float px1 = b0 * sq1.x, py1 = b1 * sq1.x, pz1 = b2 * sq1.x;
#pragma unroll
            for (int og = 0; og < 4; og++) {
                ull w00, w10, w01, w11;
                gch(W + (64 + i * 4 + og) * 64, hh0, hh1, w00, w10, w01, w11);
                const float f00 = hsum2(w00), f10 = hsum2(w10);
                const float f01 = hsum2(w01), f11 = hsum2(w11);
                vv0[(2 * og) * 3 + 0] += px0 * f00; vv0[(2 * og) * 3 + 1] += py0 * f00; vv0[(2 * og) * 3 + 2] += pz0 * f00;
                vv0[(2 * og + 1) * 3 + 0] += px0 * f10; vv0[(2 * og + 1) * 3 + 1] += py0 * f10; vv0[(2 * og + 1) * 3 + 2] += pz0 * f10;
                vv1[(2 * og) * 3 + 0] += px1 * f01; vv1[(2 * og) * 3 + 1] += py1 * f01; vv1[(2 * og) * 3 + 2] += pz1 * f01;
                vv1[(2 * og + 1) * 3 + 0] += px1 * f11; vv1[(2 * og + 1) * 3 + 1] += py1 * f11; vv1[(2 * og + 1) * 3 + 2] += pz1 * f11;
            }
        }
        {   // path5: g = 96 + i*4 + og
            const float px0 = (a1 * sq0.w - a2 * sq0.z) * INV_SQRT2;
            const float py0 = (a2 * sq0.y - a0 * sq0.w) * INV_SQRT2;
            const float pz0 = (a0 * sq0.z - a1 * sq0.y) * INV_SQRT2;
            const float px1 = (b1 * sq1.w - b2 * sq1.z) * INV_SQRT2;
            const float py1 = (b2 * sq1.y - b0 * sq1.w) * INV_SQRT2;
            const float pz1 = (b0 * sq1.z - b1 * sq1.y) * INV_SQRT2;
#pragma unroll
            for (int og = 0; og < 4; og++) {
                ull w00, w10, w01, w11;
                gch(W + (96 + i * 4 + og) * 64, hh0, hh1, w00, w10, w01, w11);
                const float f00 = hsum2(w00), f10 = hsum2(w10);
                const float f01 = hsum2(w01), f11 = hsum2(w11);
                vv0[(2 * og) * 3 + 0] += px0 * f00; vv0[(2 * og) * 3 + 1] += py0 * f00; vv0[(2 * og) * 3 + 2] += pz0 * f00;
                vv0[(2 * og + 1) * 3 + 0] += px0 * f10; vv0[(2 * og + 1) * 3 + 1] += py0 * f10; vv0[(2 * og + 1) * 3 + 2] += pz0 * f10;
                vv1[(2 * og) * 3 + 0] += px1 * f01; vv1[(2 * og) * 3 + 1] += py1 * f01; vv1[(2 * og) * 3 + 2] += pz1 * f01;
                vv1[(2 * og + 1) * 3 + 0] += px1 * f11; vv1[(2 * og + 1) * 3 + 1] += py1 * f11; vv1[(2 * og + 1) * 3 + 2] += pz1 * f11;
            }
        }
    }

    float s[24];
#pragma unroll
    for (int o = 0; o < 24; o++) {
        const float u0 = comb(vv0[o]);
        const float u1 = comb(vv1[o]);
        s[o] = par ? u1 : u0;
    }
    const int eMy = par ? ec1 : ec0;
    const bool vMy = par ? v1 : v0;
    if (vMy) {
        float* dst = g_vv + (size_t)eMy * 40 + 16;
#pragma unroll
        for (int t = 0; t < 6; t++)
            *(float4*)(dst + t * 4) = make_float4(s[t * 4 + 0] * INV_SQRT32, s[t * 4 + 1] * INV_SQRT32,
                                                  s[t * 4 + 2] * INV_SQRT32, s[t * 4 + 3] * INV_SQRT32);
    }
}

// ---------------- scatter: softmax normalize + vector reduction ----------------
__global__ void k_scatter(const void* __restrict__ ei, float* __restrict__ out, int E) {
    int e = blockIdx.x * blockDim.x + threadIdx.x;
    if (e >= E) return;
    const ll r = eidx(ei, E + e);
    const float a = sqrtf(g_ex[e] / g_z[r]);
    const float4* v = (const float4*)(g_vv + (size_t)e * 40);
    float* o = out + (size_t)r * 40;
#pragma unroll
    for (int t = 0; t < 10; t++) {
        float4 w = v[t];
        asm volatile("red.global.add.v4.f32 [%0], {%1, %2, %3, %4};"
                     :: "l"(o + t * 4), "f"(a * w.x), "f"(a * w.y), "f"(a * w.z), "f"(a * w.w)
                     : "memory");
    }
}

extern "C" void kernel_launch(void* const* d_in, const int* in_sizes, int n_in,
                              void* d_out, int out_size) {
    const float* node_ft      = (const float*)d_in[0];
    const void*  ei           = d_in[1];
    const float* edge_sh      = (const float*)d_in[2];
    const float* edge_scalars = (const float*)d_in[3];
    const float* wqs          = (const float*)d_in[4];
    const float* wqv          = (const float*)d_in[5];
    const float* fckw1        = (const float*)d_in[6];
    const float* fckw2        = (const float*)d_in[7];
    const float* fcvw1        = (const float*)d_in[8];
    const float* fcvw2        = (const float*)d_in[9];
    const float* wds          = (const float*)d_in[10];
    const float* wdv          = (const float*)d_in[11];
    float* out = (float*)d_out;

    const int N = in_sizes[0] / 40;
    const int E = in_sizes[1] / 2;
    const int gE = (E + 127) / 128;     // 128 edges per block (64 lane pairs x 2 edges)

    cudaFuncSetAttribute(k_K,  cudaFuncAttributeMaxDynamicSharedMemorySize, KK_SMEM);
    cudaFuncSetAttribute(k_Vs, cudaFuncAttributeMaxDynamicSharedMemorySize, VS_SMEM);
    cudaFuncSetAttribute(k_Vv, cudaFuncAttributeMaxDynamicSharedMemorySize, VV_SMEM);

    k_detect<<<1, 256>>>((const int*)ei, 2 * E);
    k_zero<<<(N * 40 + 255) / 256, 256>>>(out, N);
    k_query<<<(N + 255) / 256, 256>>>(node_ft, wqs, wqv, wds, wdv, N);
    k_K<<<gE, 128, KK_SMEM>>>(node_ft, ei, edge_sh, edge_scalars, fckw1, fckw2, E);
    k_Vs<<<gE, 128, VS_SMEM>>>(node_ft, ei, edge_sh, edge_scalars, fcvw1, fcvw2, E);
    k_Vv<<<gE, 128, VV_SMEM>>>(node_ft, ei, edge_sh, edge_scalars, fcvw1, fcvw2, E);
    k_scatter<<<(E + 255) / 256, 256>>>(ei, out, E);
}